// round 2
// baseline (speedup 1.0000x reference)
#include <cuda_runtime.h>
#include <math.h>

#define BB 16
#define LL 1023
#define SS 1024
#define DD 128
#define DVAL 64
#define NDEMO 16
#define HH 8
#define DH 16
#define NLAY 2
#define DFF 512
#define MLPH 256

// ---------------- device scratch (no allocs allowed) ----------------
__device__ float g_x[BB * SS * DD];
__device__ float g_q[BB * SS * DD];
__device__ float g_k[BB * SS * DD];
__device__ float g_v[BB * SS * DD];
__device__ float g_o[BB * SS * DD];

// ---------------- helpers ----------------
__device__ __forceinline__ float block_sum128(float v, float* red) {
    #pragma unroll
    for (int o = 16; o > 0; o >>= 1) v += __shfl_xor_sync(0xffffffff, v, o);
    int t = threadIdx.x;
    if ((t & 31) == 0) red[t >> 5] = v;
    __syncthreads();
    float s = red[0] + red[1] + red[2] + red[3];
    __syncthreads();
    return s;
}

__device__ __forceinline__ float half_sum256(float v, float* red) {
    #pragma unroll
    for (int o = 16; o > 0; o >>= 1) v += __shfl_xor_sync(0xffffffff, v, o);
    int t = threadIdx.x;
    if ((t & 31) == 0) red[t >> 5] = v;
    __syncthreads();
    int base = (t >> 7) * 4;
    float s = red[base] + red[base + 1] + red[base + 2] + red[base + 3];
    __syncthreads();
    return s;
}

// ---------------- embedding ----------------
__global__ __launch_bounds__(256) void embed_kernel(
    const float* __restrict__ demo, const float* __restrict__ times,
    const float* __restrict__ values, const float* __restrict__ timescales,
    const float* __restrict__ W_demo, const float* __restrict__ b_demo,
    const float* __restrict__ W_val, const float* __restrict__ b_val) {
    int idx = blockIdx.x * blockDim.x + threadIdx.x;
    if (idx >= BB * SS * DD) return;
    int d = idx % DD;
    int s = (idx / DD) % SS;
    int b = idx / (DD * SS);
    float out;
    if (s == 0) {
        float acc = b_demo[d];
        #pragma unroll
        for (int k = 0; k < NDEMO; k++) acc += demo[b * NDEMO + k] * W_demo[k * DD + d];
        out = acc;
    } else {
        int t = s - 1;
        float acc = b_val[d];
        const float4* vrow = (const float4*)(values + (b * LL + t) * DVAL);
        #pragma unroll
        for (int k4 = 0; k4 < DVAL / 4; k4++) {
            float4 vv = vrow[k4];
            acc += vv.x * W_val[(k4 * 4 + 0) * DD + d];
            acc += vv.y * W_val[(k4 * 4 + 1) * DD + d];
            acc += vv.z * W_val[(k4 * 4 + 2) * DD + d];
            acc += vv.w * W_val[(k4 * 4 + 3) * DD + d];
        }
        float tm = times[b * LL + t];
        float st = tm / timescales[d & 63];
        out = acc + ((d < 64) ? sinf(st) : cosf(st));
    }
    g_x[idx] = out;
}

// ---------------- fused QKV projection: 16 rows per block ----------------
__global__ __launch_bounds__(128) void qkv_kernel(
    const float* __restrict__ Wq, const float* __restrict__ bq,
    const float* __restrict__ Wk, const float* __restrict__ bk,
    const float* __restrict__ Wv, const float* __restrict__ bv) {
    __shared__ float xs[16][DD];
    int row0 = blockIdx.x * 16;
    int t = threadIdx.x;  // output column 0..127
    #pragma unroll
    for (int r = 0; r < 16; r++) xs[r][t] = g_x[(row0 + r) * DD + t];
    __syncthreads();
    {
        float acc[16];
        float bias = bq[t];
        #pragma unroll
        for (int r = 0; r < 16; r++) acc[r] = bias;
        for (int k = 0; k < DD; k++) {
            float w = Wq[k * DD + t];
            #pragma unroll
            for (int r = 0; r < 16; r++) acc[r] += xs[r][k] * w;
        }
        #pragma unroll
        for (int r = 0; r < 16; r++) g_q[(row0 + r) * DD + t] = acc[r];
    }
    {
        float acc[16];
        float bias = bk[t];
        #pragma unroll
        for (int r = 0; r < 16; r++) acc[r] = bias;
        for (int k = 0; k < DD; k++) {
            float w = Wk[k * DD + t];
            #pragma unroll
            for (int r = 0; r < 16; r++) acc[r] += xs[r][k] * w;
        }
        #pragma unroll
        for (int r = 0; r < 16; r++) g_k[(row0 + r) * DD + t] = acc[r];
    }
    {
        float acc[16];
        float bias = bv[t];
        #pragma unroll
        for (int r = 0; r < 16; r++) acc[r] = bias;
        for (int k = 0; k < DD; k++) {
            float w = Wv[k * DD + t];
            #pragma unroll
            for (int r = 0; r < 16; r++) acc[r] += xs[r][k] * w;
        }
        #pragma unroll
        for (int r = 0; r < 16; r++) g_v[(row0 + r) * DD + t] = acc[r];
    }
}

// ---------------- flash attention: block = (qtile=32, h, b), 256 threads ----------------
__global__ __launch_bounds__(256) void attn_kernel(const int* __restrict__ length) {
    const int qt = blockIdx.x, h = blockIdx.y, b = blockIdx.z;
    __shared__ float Qs[32][17];
    __shared__ float Ks[32][17];
    __shared__ float Vs[32][17];
    __shared__ float Ps[32][33];
    int t = threadIdx.x;
    int q_local = t >> 3;   // 0..31
    int lane8 = t & 7;      // 0..7
    int valid_len = length[b] + 1;

    for (int i = t; i < 32 * DH; i += 256) {
        int r = i >> 4, d = i & 15;
        Qs[r][d] = g_q[(b * SS + qt * 32 + r) * DD + h * DH + d];
    }

    float m = -1e30f, l = 0.f;
    float o0 = 0.f, o1 = 0.f;

    const float* qrow = &Qs[0][0];  // hoisted base

    for (int c = 0; c < 32; c++) {
        __syncthreads();
        for (int i = t; i < 32 * DH; i += 256) {
            int r = i >> 4, d = i & 15;
            int src = (b * SS + c * 32 + r) * DD + h * DH + d;
            Ks[r][d] = g_k[src];
            Vs[r][d] = g_v[src];
        }
        __syncthreads();

        float sc[4];
        float cmax = -1e30f;
        #pragma unroll
        for (int j = 0; j < 4; j++) {
            int kk = lane8 + 8 * j;
            float acc = 0.f;
            #pragma unroll
            for (int d = 0; d < DH; d++) acc += qrow[q_local * 17 + d] * Ks[kk][d];
            acc *= 0.25f;  // 1/sqrt(16)
            if (c * 32 + kk >= valid_len) acc = -1e30f;
            sc[j] = acc;
            cmax = fmaxf(cmax, acc);
        }
        #pragma unroll
        for (int o = 4; o > 0; o >>= 1)
            cmax = fmaxf(cmax, __shfl_xor_sync(0xffffffff, cmax, o, 8));

        float m_new = fmaxf(m, cmax);
        float scale = __expf(m - m_new);
        float lsum = 0.f;
        #pragma unroll
        for (int j = 0; j < 4; j++) {
            float p = __expf(sc[j] - m_new);
            Ps[q_local][lane8 + 8 * j] = p;
            lsum += p;
        }
        #pragma unroll
        for (int o = 4; o > 0; o >>= 1)
            lsum += __shfl_xor_sync(0xffffffff, lsum, o, 8);
        l = l * scale + lsum;
        __syncwarp();

        float a0 = 0.f, a1 = 0.f;
        #pragma unroll
        for (int kk = 0; kk < 32; kk++) {
            float p = Ps[q_local][kk];
            a0 += p * Vs[kk][lane8];
            a1 += p * Vs[kk][lane8 + 8];
        }
        o0 = o0 * scale + a0;
        o1 = o1 * scale + a1;
        m = m_new;
    }

    float inv = 1.f / l;
    int row = b * SS + qt * 32 + q_local;
    g_o[row * DD + h * DH + lane8] = o0 * inv;
    g_o[row * DD + h * DH + lane8 + 8] = o1 * inv;
}

// ---------------- O-proj + residual + LN1: 16 rows per block ----------------
__global__ __launch_bounds__(128) void oproj_ln_kernel(
    const float* __restrict__ Wo, const float* __restrict__ bo,
    const float* __restrict__ g1, const float* __restrict__ be1) {
    __shared__ float os[16][DD];
    __shared__ float ys[16][DD];
    __shared__ float red[4];
    int row0 = blockIdx.x * 16;
    int t = threadIdx.x;
    #pragma unroll
    for (int r = 0; r < 16; r++) os[r][t] = g_o[(row0 + r) * DD + t];
    __syncthreads();
    {
        float acc[16];
        float bias = bo[t];
        #pragma unroll
        for (int r = 0; r < 16; r++) acc[r] = bias;
        for (int k = 0; k < DD; k++) {
            float w = Wo[k * DD + t];
            #pragma unroll
            for (int r = 0; r < 16; r++) acc[r] += os[r][k] * w;
        }
        #pragma unroll
        for (int r = 0; r < 16; r++) ys[r][t] = acc[r] + g_x[(row0 + r) * DD + t];
    }
    __syncthreads();
    float g = g1[t], bb = be1[t];
    for (int r = 0; r < 16; r++) {
        float v = ys[r][t];
        float mean = block_sum128(v, red) * (1.f / DD);
        float dv = v - mean;
        float var = block_sum128(dv * dv, red) * (1.f / DD);
        g_x[(row0 + r) * DD + t] = dv * rsqrtf(var + 1e-3f) * g + bb;
    }
}

// ---------------- FFN + residual + LN2: 8 rows per block, 256 threads ----------------
__global__ __launch_bounds__(256) void ffn_kernel(
    const float* __restrict__ W1, const float* __restrict__ b1,
    const float* __restrict__ W2, const float* __restrict__ b2,
    const float* __restrict__ g2, const float* __restrict__ be2) {
    __shared__ float xs[8][DD];
    __shared__ float hs[8][DFF];
    __shared__ float ys[8][DD];
    __shared__ float red[8];
    int row0 = blockIdx.x * 8;
    int t = threadIdx.x;

    {
        const float4* src = (const float4*)(g_x + row0 * DD);
        float4* dst = (float4*)(&xs[0][0]);
        if (t < 8 * DD / 4) dst[t] = src[t];
    }
    __syncthreads();

    {
        float acc0[8], acc1[8];
        float bi0 = b1[t], bi1 = b1[t + 256];
        #pragma unroll
        for (int r = 0; r < 8; r++) { acc0[r] = bi0; acc1[r] = bi1; }
        for (int k = 0; k < DD; k++) {
            float w0 = W1[k * DFF + t];
            float w1 = W1[k * DFF + t + 256];
            #pragma unroll
            for (int r = 0; r < 8; r++) {
                float xv = xs[r][k];
                acc0[r] += xv * w0;
                acc1[r] += xv * w1;
            }
        }
        #pragma unroll
        for (int r = 0; r < 8; r++) {
            hs[r][t] = fmaxf(acc0[r], 0.f);
            hs[r][t + 256] = fmaxf(acc1[r], 0.f);
        }
    }
    __syncthreads();

    {
        int d = t & 127, rg = t >> 7;
        float acc[4];
        float bias = b2[d];
        #pragma unroll
        for (int i = 0; i < 4; i++) acc[i] = bias;
        for (int j = 0; j < DFF; j++) {
            float w = W2[j * DD + d];
            #pragma unroll
            for (int i = 0; i < 4; i++) acc[i] += hs[rg * 4 + i][j] * w;
        }
        #pragma unroll
        for (int i = 0; i < 4; i++) {
            int r = rg * 4 + i;
            ys[r][d] = acc[i] + xs[r][d];
        }
    }
    __syncthreads();

    int d = t & 127, half = t >> 7;
    float g = g2[d], bb = be2[d];
    for (int rp = 0; rp < 4; rp++) {
        int r = rp * 2 + half;
        float v = ys[r][d];
        float mean = half_sum256(v, red) * (1.f / DD);
        float dv = v - mean;
        float var = half_sum256(dv * dv, red) * (1.f / DD);
        g_x[(row0 + r) * DD + d] = dv * rsqrtf(var + 1e-3f) * g + bb;
    }
}

// ---------------- masked mean-pool + MLP head + sigmoid ----------------
__global__ __launch_bounds__(256) void head_kernel(
    const int* __restrict__ length,
    const float* __restrict__ Wm1, const float* __restrict__ bm1,
    const float* __restrict__ Wm2, const float* __restrict__ bm2,
    float* __restrict__ out) {
    int b = blockIdx.x;
    int t = threadIdx.x;
    __shared__ float agg[DD];
    __shared__ float hh[MLPH];
    __shared__ float red[8];
    int cnt = length[b] + 1;
    if (t < DD) {
        float s = 0.f;
        for (int ss = 0; ss < cnt; ss++) s += g_x[(b * SS + ss) * DD + t];
        agg[t] = s / (float)cnt;
    }
    __syncthreads();
    {
        float acc = bm1[t];
        for (int k = 0; k < DD; k++) acc += agg[k] * Wm1[k * MLPH + t];
        hh[t] = fmaxf(acc, 0.f);
    }
    __syncthreads();
    float v = hh[t] * Wm2[t];
    #pragma unroll
    for (int o = 16; o > 0; o >>= 1) v += __shfl_xor_sync(0xffffffff, v, o);
    if ((t & 31) == 0) red[t >> 5] = v;
    __syncthreads();
    if (t == 0) {
        float s = 0.f;
        #pragma unroll
        for (int i = 0; i < 8; i++) s += red[i];
        s += bm2[0];
        out[b] = 1.f / (1.f + __expf(-s));
    }
}

// ---------------- launch ----------------
extern "C" void kernel_launch(void* const* d_in, const int* in_sizes, int n_in,
                              void* d_out, int out_size) {
    (void)in_sizes; (void)n_in; (void)out_size;
    const float* demo       = (const float*)d_in[0];
    const float* times      = (const float*)d_in[1];
    const float* values     = (const float*)d_in[2];
    const int*   length     = (const int*)d_in[3];
    const float* timescales = (const float*)d_in[4];
    const float* W_demo = (const float*)d_in[5];
    const float* b_demo = (const float*)d_in[6];
    const float* W_val  = (const float*)d_in[7];
    const float* b_val  = (const float*)d_in[8];
    const float* Wq = (const float*)d_in[9];
    const float* bq = (const float*)d_in[10];
    const float* Wk = (const float*)d_in[11];
    const float* bk = (const float*)d_in[12];
    const float* Wv = (const float*)d_in[13];
    const float* bv = (const float*)d_in[14];
    const float* Wo = (const float*)d_in[15];
    const float* bo = (const float*)d_in[16];
    const float* ln1g = (const float*)d_in[17];
    const float* ln1b = (const float*)d_in[18];
    const float* W1 = (const float*)d_in[19];
    const float* b1 = (const float*)d_in[20];
    const float* W2 = (const float*)d_in[21];
    const float* b2 = (const float*)d_in[22];
    const float* ln2g = (const float*)d_in[23];
    const float* ln2b = (const float*)d_in[24];
    const float* Wm1 = (const float*)d_in[25];
    const float* bm1 = (const float*)d_in[26];
    const float* Wm2 = (const float*)d_in[27];
    const float* bm2 = (const float*)d_in[28];
    float* out = (float*)d_out;

    embed_kernel<<<(BB * SS * DD + 255) / 256, 256>>>(
        demo, times, values, timescales, W_demo, b_demo, W_val, b_val);

    for (int l = 0; l < NLAY; l++) {
        qkv_kernel<<<BB * SS / 16, 128>>>(
            Wq + l * DD * DD, bq + l * DD,
            Wk + l * DD * DD, bk + l * DD,
            Wv + l * DD * DD, bv + l * DD);
        dim3 ag(SS / 32, HH, BB);
        attn_kernel<<<ag, 256>>>(length);
        oproj_ln_kernel<<<BB * SS / 16, 128>>>(
            Wo + l * DD * DD, bo + l * DD, ln1g + l * DD, ln1b + l * DD);
        ffn_kernel<<<BB * SS / 8, 256>>>(
            W1 + l * DD * DFF, b1 + l * DFF,
            W2 + l * DFF * DD, b2 + l * DD,
            ln2g + l * DD, ln2b + l * DD);
    }

    head_kernel<<<BB, 256>>>(length, Wm1, bm1, Wm2, bm2, out);
}

// round 3
// speedup vs baseline: 2.9866x; 2.9866x over previous
#include <cuda_runtime.h>
#include <math.h>

#define BB 16
#define LL 1023
#define SS 1024
#define DD 128
#define DVAL 64
#define NDEMO 16
#define HH 8
#define DH 16
#define NLAY 2
#define DFF 512
#define MLPH 256

// ---------------- device scratch (no allocs allowed) ----------------
__device__ float g_x[BB * SS * DD];
__device__ float g_q[BB * SS * DD];
__device__ float g_k[BB * SS * DD];
__device__ float g_v[BB * SS * DD];
__device__ float g_o[BB * SS * DD];

__device__ __forceinline__ float dot4(float4 a, float4 b) {
    return a.x * b.x + a.y * b.y + a.z * b.z + a.w * b.w;
}

// ---------------- embedding ----------------
__global__ __launch_bounds__(256) void embed_kernel(
    const float* __restrict__ demo, const float* __restrict__ times,
    const float* __restrict__ values, const float* __restrict__ timescales,
    const float* __restrict__ W_demo, const float* __restrict__ b_demo,
    const float* __restrict__ W_val, const float* __restrict__ b_val,
    const int* __restrict__ length) {
    int idx = blockIdx.x * blockDim.x + threadIdx.x;
    if (idx >= BB * SS * DD) return;
    int d = idx % DD;
    int s = (idx / DD) % SS;
    int b = idx / (DD * SS);
    if (s > length[b]) return;  // masked everywhere downstream
    float out;
    if (s == 0) {
        float acc = b_demo[d];
        #pragma unroll
        for (int k = 0; k < NDEMO; k++) acc += demo[b * NDEMO + k] * W_demo[k * DD + d];
        out = acc;
    } else {
        int t = s - 1;
        float acc = b_val[d];
        const float4* vrow = (const float4*)(values + (b * LL + t) * DVAL);
        #pragma unroll
        for (int k4 = 0; k4 < DVAL / 4; k4++) {
            float4 vv = vrow[k4];
            acc += vv.x * W_val[(k4 * 4 + 0) * DD + d];
            acc += vv.y * W_val[(k4 * 4 + 1) * DD + d];
            acc += vv.z * W_val[(k4 * 4 + 2) * DD + d];
            acc += vv.w * W_val[(k4 * 4 + 3) * DD + d];
        }
        float tm = times[b * LL + t];
        float st = tm / timescales[d & 63];
        out = acc + ((d < 64) ? __sinf(st) : __cosf(st));
    }
    g_x[idx] = out;
}

// ---------------- fused QKV projection: 16 rows/block, k-unroll-4 ----------------
__global__ __launch_bounds__(128) void qkv_kernel(
    const int* __restrict__ length,
    const float* __restrict__ Wq, const float* __restrict__ bq,
    const float* __restrict__ Wk, const float* __restrict__ bk,
    const float* __restrict__ Wv, const float* __restrict__ bv) {
    int row0 = blockIdx.x * 16;
    int b = row0 >> 10;
    int valid_len = length[b] + 1;
    if ((row0 & (SS - 1)) >= valid_len) return;
    __shared__ float xs[16][DD];
    int t = threadIdx.x;
    #pragma unroll
    for (int r = 0; r < 16; r++) xs[r][t] = g_x[(row0 + r) * DD + t];
    __syncthreads();
    float aq[16], ak[16], av[16];
    float biq = bq[t], bik = bk[t], biv = bv[t];
    #pragma unroll
    for (int r = 0; r < 16; r++) { aq[r] = biq; ak[r] = bik; av[r] = biv; }
    for (int k = 0; k < DD; k += 4) {
        float wq0 = Wq[(k + 0) * DD + t], wq1 = Wq[(k + 1) * DD + t];
        float wq2 = Wq[(k + 2) * DD + t], wq3 = Wq[(k + 3) * DD + t];
        float wk0 = Wk[(k + 0) * DD + t], wk1 = Wk[(k + 1) * DD + t];
        float wk2 = Wk[(k + 2) * DD + t], wk3 = Wk[(k + 3) * DD + t];
        float wv0 = Wv[(k + 0) * DD + t], wv1 = Wv[(k + 1) * DD + t];
        float wv2 = Wv[(k + 2) * DD + t], wv3 = Wv[(k + 3) * DD + t];
        #pragma unroll
        for (int r = 0; r < 16; r++) {
            float4 x4 = *(const float4*)&xs[r][k];
            aq[r] += x4.x * wq0 + x4.y * wq1 + x4.z * wq2 + x4.w * wq3;
            ak[r] += x4.x * wk0 + x4.y * wk1 + x4.z * wk2 + x4.w * wk3;
            av[r] += x4.x * wv0 + x4.y * wv1 + x4.z * wv2 + x4.w * wv3;
        }
    }
    #pragma unroll
    for (int r = 0; r < 16; r++) {
        g_q[(row0 + r) * DD + t] = aq[r];
        g_k[(row0 + r) * DD + t] = ak[r];
        g_v[(row0 + r) * DD + t] = av[r];
    }
}

// ---------------- flash attention: thread = 1 query, regs only ----------------
__global__ __launch_bounds__(128) void attn_kernel(const int* __restrict__ length) {
    const int qt = blockIdx.x, h = blockIdx.y, b = blockIdx.z;
    int valid_len = length[b] + 1;
    if (qt * 128 >= valid_len) return;
    __shared__ float Ks[32][16];
    __shared__ float Vs[32][16];
    int t = threadIdx.x;
    int qrow = b * SS + qt * 128 + t;
    const float4* qp = (const float4*)(g_q + qrow * DD + h * DH);
    float4 q0 = qp[0], q1 = qp[1], q2 = qp[2], q3 = qp[3];
    float m = -1e30f, l = 0.f;
    float4 o0 = {0,0,0,0}, o1 = {0,0,0,0}, o2 = {0,0,0,0}, o3 = {0,0,0,0};
    int nch = (valid_len + 31) >> 5;
    int kk_ld = t >> 2, part_ld = t & 3;
    for (int c = 0; c < nch; c++) {
        __syncthreads();
        {
            int src = (b * SS + c * 32 + kk_ld) * DD + h * DH + part_ld * 4;
            ((float4*)Ks)[t] = *(const float4*)(g_k + src);
            ((float4*)Vs)[t] = *(const float4*)(g_v + src);
        }
        __syncthreads();
        int limit = valid_len - c * 32;
        float sc[32];
        float cmax = -1e30f;
        #pragma unroll
        for (int kk = 0; kk < 32; kk++) {
            const float4* kp = (const float4*)Ks[kk];
            float s = dot4(q0, kp[0]) + dot4(q1, kp[1]) + dot4(q2, kp[2]) + dot4(q3, kp[3]);
            s *= 0.25f;  // 1/sqrt(16)
            sc[kk] = (kk < limit) ? s : -1e30f;
            cmax = fmaxf(cmax, sc[kk]);
        }
        float m_new = fmaxf(m, cmax);
        float scale = __expf(m - m_new);
        float lsum = 0.f;
        #pragma unroll
        for (int kk = 0; kk < 32; kk++) {
            float p = __expf(sc[kk] - m_new);
            sc[kk] = p;
            lsum += p;
        }
        l = l * scale + lsum;
        o0.x *= scale; o0.y *= scale; o0.z *= scale; o0.w *= scale;
        o1.x *= scale; o1.y *= scale; o1.z *= scale; o1.w *= scale;
        o2.x *= scale; o2.y *= scale; o2.z *= scale; o2.w *= scale;
        o3.x *= scale; o3.y *= scale; o3.z *= scale; o3.w *= scale;
        #pragma unroll
        for (int kk = 0; kk < 32; kk++) {
            float p = sc[kk];
            const float4* vp = (const float4*)Vs[kk];
            float4 v0 = vp[0], v1 = vp[1], v2 = vp[2], v3 = vp[3];
            o0.x += p * v0.x; o0.y += p * v0.y; o0.z += p * v0.z; o0.w += p * v0.w;
            o1.x += p * v1.x; o1.y += p * v1.y; o1.z += p * v1.z; o1.w += p * v1.w;
            o2.x += p * v2.x; o2.y += p * v2.y; o2.z += p * v2.z; o2.w += p * v2.w;
            o3.x += p * v3.x; o3.y += p * v3.y; o3.z += p * v3.z; o3.w += p * v3.w;
        }
        m = m_new;
    }
    float inv = 1.f / l;
    float4* op = (float4*)(g_o + qrow * DD + h * DH);
    o0.x *= inv; o0.y *= inv; o0.z *= inv; o0.w *= inv;
    o1.x *= inv; o1.y *= inv; o1.z *= inv; o1.w *= inv;
    o2.x *= inv; o2.y *= inv; o2.z *= inv; o2.w *= inv;
    o3.x *= inv; o3.y *= inv; o3.z *= inv; o3.w *= inv;
    op[0] = o0; op[1] = o1; op[2] = o2; op[3] = o3;
}

// ---------------- O-proj + residual + LN1: 16 rows/block ----------------
__global__ __launch_bounds__(128) void oproj_ln_kernel(
    const int* __restrict__ length,
    const float* __restrict__ Wo, const float* __restrict__ bo,
    const float* __restrict__ g1, const float* __restrict__ be1) {
    int row0 = blockIdx.x * 16;
    int b = row0 >> 10;
    int valid_len = length[b] + 1;
    if ((row0 & (SS - 1)) >= valid_len) return;
    __shared__ float os[16][DD];
    __shared__ float ys[16][DD];
    __shared__ float mean_s[16], rstd_s[16];
    int t = threadIdx.x;
    #pragma unroll
    for (int r = 0; r < 16; r++) os[r][t] = g_o[(row0 + r) * DD + t];
    __syncthreads();
    float acc[16];
    float bias = bo[t];
    #pragma unroll
    for (int r = 0; r < 16; r++) acc[r] = bias;
    for (int k = 0; k < DD; k += 4) {
        float w0 = Wo[(k + 0) * DD + t], w1 = Wo[(k + 1) * DD + t];
        float w2 = Wo[(k + 2) * DD + t], w3 = Wo[(k + 3) * DD + t];
        #pragma unroll
        for (int r = 0; r < 16; r++) {
            float4 x4 = *(const float4*)&os[r][k];
            acc[r] += x4.x * w0 + x4.y * w1 + x4.z * w2 + x4.w * w3;
        }
    }
    #pragma unroll
    for (int r = 0; r < 16; r++) ys[r][t] = acc[r] + g_x[(row0 + r) * DD + t];
    __syncthreads();
    // warp-per-row LN stats: warp w handles rows w, w+4, w+8, w+12
    int lane = t & 31, w = t >> 5;
    #pragma unroll
    for (int i = 0; i < 4; i++) {
        int r = (i << 2) | w;
        float s1 = 0.f, s2 = 0.f;
        #pragma unroll
        for (int j = 0; j < 4; j++) {
            float v = ys[r][lane + 32 * j];
            s1 += v; s2 += v * v;
        }
        #pragma unroll
        for (int o = 16; o > 0; o >>= 1) {
            s1 += __shfl_xor_sync(0xffffffff, s1, o);
            s2 += __shfl_xor_sync(0xffffffff, s2, o);
        }
        if (lane == 0) {
            float mu = s1 * (1.f / DD);
            float var = fmaxf(s2 * (1.f / DD) - mu * mu, 0.f);
            mean_s[r] = mu;
            rstd_s[r] = rsqrtf(var + 1e-3f);
        }
    }
    __syncthreads();
    float g = g1[t], bb = be1[t];
    #pragma unroll
    for (int r = 0; r < 16; r++)
        g_x[(row0 + r) * DD + t] = (ys[r][t] - mean_s[r]) * rstd_s[r] * g + bb;
}

// ---------------- FFN + residual + LN2: 8 rows/block, 256 threads ----------------
__global__ __launch_bounds__(256) void ffn_kernel(
    const int* __restrict__ length,
    const float* __restrict__ W1, const float* __restrict__ b1,
    const float* __restrict__ W2, const float* __restrict__ b2,
    const float* __restrict__ g2, const float* __restrict__ be2) {
    int row0 = blockIdx.x * 8;
    int b = row0 >> 10;
    int valid_len = length[b] + 1;
    if ((row0 & (SS - 1)) >= valid_len) return;
    __shared__ float xs[8][DD];
    __shared__ float hs[8][DFF];
    __shared__ float ys[8][DD];
    __shared__ float mean_s[8], rstd_s[8];
    int t = threadIdx.x;

    {
        const float4* src = (const float4*)(g_x + row0 * DD);
        if (t < 8 * DD / 4) ((float4*)(&xs[0][0]))[t] = src[t];
    }
    __syncthreads();

    // hidden = relu(x @ W1 + b1): cols t and t+256
    {
        float a0[8], a1[8];
        float bi0 = b1[t], bi1 = b1[t + 256];
        #pragma unroll
        for (int r = 0; r < 8; r++) { a0[r] = bi0; a1[r] = bi1; }
        for (int k = 0; k < DD; k += 4) {
            float u0 = W1[(k + 0) * DFF + t], u1 = W1[(k + 1) * DFF + t];
            float u2 = W1[(k + 2) * DFF + t], u3 = W1[(k + 3) * DFF + t];
            float v0 = W1[(k + 0) * DFF + t + 256], v1 = W1[(k + 1) * DFF + t + 256];
            float v2 = W1[(k + 2) * DFF + t + 256], v3 = W1[(k + 3) * DFF + t + 256];
            #pragma unroll
            for (int r = 0; r < 8; r++) {
                float4 x4 = *(const float4*)&xs[r][k];
                a0[r] += x4.x * u0 + x4.y * u1 + x4.z * u2 + x4.w * u3;
                a1[r] += x4.x * v0 + x4.y * v1 + x4.z * v2 + x4.w * v3;
            }
        }
        #pragma unroll
        for (int r = 0; r < 8; r++) {
            hs[r][t] = fmaxf(a0[r], 0.f);
            hs[r][t + 256] = fmaxf(a1[r], 0.f);
        }
    }
    __syncthreads();

    // f = hidden @ W2 + b2 + residual
    {
        int d = t & 127, rg = t >> 7;
        float acc[4];
        float bias = b2[d];
        #pragma unroll
        for (int i = 0; i < 4; i++) acc[i] = bias;
        for (int j = 0; j < DFF; j += 4) {
            float w0 = W2[(j + 0) * DD + d], w1 = W2[(j + 1) * DD + d];
            float w2 = W2[(j + 2) * DD + d], w3 = W2[(j + 3) * DD + d];
            #pragma unroll
            for (int i = 0; i < 4; i++) {
                float4 h4 = *(const float4*)&hs[rg * 4 + i][j];
                acc[i] += h4.x * w0 + h4.y * w1 + h4.z * w2 + h4.w * w3;
            }
        }
        #pragma unroll
        for (int i = 0; i < 4; i++) {
            int r = rg * 4 + i;
            ys[r][d] = acc[i] + xs[r][d];
        }
    }
    __syncthreads();

    // LN stats: warp w -> row w
    {
        int lane = t & 31, w = t >> 5;
        float s1 = 0.f, s2 = 0.f;
        #pragma unroll
        for (int j = 0; j < 4; j++) {
            float v = ys[w][lane + 32 * j];
            s1 += v; s2 += v * v;
        }
        #pragma unroll
        for (int o = 16; o > 0; o >>= 1) {
            s1 += __shfl_xor_sync(0xffffffff, s1, o);
            s2 += __shfl_xor_sync(0xffffffff, s2, o);
        }
        if (lane == 0) {
            float mu = s1 * (1.f / DD);
            float var = fmaxf(s2 * (1.f / DD) - mu * mu, 0.f);
            mean_s[w] = mu;
            rstd_s[w] = rsqrtf(var + 1e-3f);
        }
    }
    __syncthreads();
    {
        int d = t & 127, rg = t >> 7;
        float g = g2[d], bb = be2[d];
        #pragma unroll
        for (int i = 0; i < 4; i++) {
            int r = rg * 4 + i;
            g_x[(row0 + r) * DD + d] = (ys[r][d] - mean_s[r]) * rstd_s[r] * g + bb;
        }
    }
}

// ---------------- masked mean-pool + MLP head + sigmoid ----------------
__global__ __launch_bounds__(256) void head_kernel(
    const int* __restrict__ length,
    const float* __restrict__ Wm1, const float* __restrict__ bm1,
    const float* __restrict__ Wm2, const float* __restrict__ bm2,
    float* __restrict__ out) {
    int b = blockIdx.x;
    int t = threadIdx.x;
    __shared__ float part[2][DD];
    __shared__ float agg[DD];
    __shared__ float hh[MLPH];
    __shared__ float red[8];
    int cnt = length[b] + 1;
    int d = t & 127, grp = t >> 7;
    float s0 = 0.f, s1 = 0.f, s2 = 0.f, s3 = 0.f;
    int ss = grp;
    for (; ss + 6 < cnt; ss += 8) {
        s0 += g_x[(b * SS + ss) * DD + d];
        s1 += g_x[(b * SS + ss + 2) * DD + d];
        s2 += g_x[(b * SS + ss + 4) * DD + d];
        s3 += g_x[(b * SS + ss + 6) * DD + d];
    }
    for (; ss < cnt; ss += 2) s0 += g_x[(b * SS + ss) * DD + d];
    part[grp][d] = s0 + s1 + s2 + s3;
    __syncthreads();
    if (t < DD) agg[t] = (part[0][t] + part[1][t]) / (float)cnt;
    __syncthreads();
    {
        float acc = bm1[t];
        #pragma unroll 8
        for (int k = 0; k < DD; k++) acc += agg[k] * Wm1[k * MLPH + t];
        hh[t] = fmaxf(acc, 0.f);
    }
    __syncthreads();
    float v = hh[t] * Wm2[t];
    #pragma unroll
    for (int o = 16; o > 0; o >>= 1) v += __shfl_xor_sync(0xffffffff, v, o);
    if ((t & 31) == 0) red[t >> 5] = v;
    __syncthreads();
    if (t == 0) {
        float s = 0.f;
        #pragma unroll
        for (int i = 0; i < 8; i++) s += red[i];
        s += bm2[0];
        out[b] = 1.f / (1.f + __expf(-s));
    }
}

// ---------------- launch ----------------
extern "C" void kernel_launch(void* const* d_in, const int* in_sizes, int n_in,
                              void* d_out, int out_size) {
    (void)in_sizes; (void)n_in; (void)out_size;
    const float* demo       = (const float*)d_in[0];
    const float* times      = (const float*)d_in[1];
    const float* values     = (const float*)d_in[2];
    const int*   length     = (const int*)d_in[3];
    const float* timescales = (const float*)d_in[4];
    const float* W_demo = (const float*)d_in[5];
    const float* b_demo = (const float*)d_in[6];
    const float* W_val  = (const float*)d_in[7];
    const float* b_val  = (const float*)d_in[8];
    const float* Wq = (const float*)d_in[9];
    const float* bq = (const float*)d_in[10];
    const float* Wk = (const float*)d_in[11];
    const float* bk = (const float*)d_in[12];
    const float* Wv = (const float*)d_in[13];
    const float* bv = (const float*)d_in[14];
    const float* Wo = (const float*)d_in[15];
    const float* bo = (const float*)d_in[16];
    const float* ln1g = (const float*)d_in[17];
    const float* ln1b = (const float*)d_in[18];
    const float* W1 = (const float*)d_in[19];
    const float* b1 = (const float*)d_in[20];
    const float* W2 = (const float*)d_in[21];
    const float* b2 = (const float*)d_in[22];
    const float* ln2g = (const float*)d_in[23];
    const float* ln2b = (const float*)d_in[24];
    const float* Wm1 = (const float*)d_in[25];
    const float* bm1 = (const float*)d_in[26];
    const float* Wm2 = (const float*)d_in[27];
    const float* bm2 = (const float*)d_in[28];
    float* out = (float*)d_out;

    embed_kernel<<<(BB * SS * DD + 255) / 256, 256>>>(
        demo, times, values, timescales, W_demo, b_demo, W_val, b_val, length);

    for (int l = 0; l < NLAY; l++) {
        qkv_kernel<<<BB * SS / 16, 128>>>(length,
            Wq + l * DD * DD, bq + l * DD,
            Wk + l * DD * DD, bk + l * DD,
            Wv + l * DD * DD, bv + l * DD);
        dim3 ag(SS / 128, HH, BB);
        attn_kernel<<<ag, 128>>>(length);
        oproj_ln_kernel<<<BB * SS / 16, 128>>>(length,
            Wo + l * DD * DD, bo + l * DD, ln1g + l * DD, ln1b + l * DD);
        ffn_kernel<<<BB * SS / 8, 256>>>(length,
            W1 + l * DD * DFF, b1 + l * DFF,
            W2 + l * DFF * DD, b2 + l * DD,
            ln2g + l * DD, ln2b + l * DD);
    }

    head_kernel<<<BB, 256>>>(length, Wm1, bm1, Wm2, bm2, out);
}

// round 4
// speedup vs baseline: 3.9567x; 1.3248x over previous
#include <cuda_runtime.h>
#include <math.h>

#define BB 16
#define LL 1023
#define SS 1024
#define DD 128
#define DVAL 64
#define NDEMO 16
#define HH 8
#define DH 16
#define NLAY 2
#define DFF 512
#define MLPH 256

// ---------------- device scratch (no allocs allowed) ----------------
__device__ float g_x[BB * SS * DD];
__device__ float g_q[BB * SS * DD];
__device__ float g_k[BB * SS * DD];
__device__ float g_v[BB * SS * DD];
__device__ float g_o[BB * SS * DD];

__device__ __forceinline__ float dot4(float4 a, float4 b) {
    return a.x * b.x + a.y * b.y + a.z * b.z + a.w * b.w;
}

__device__ __forceinline__ unsigned f2tf(float x) {
    unsigned r;
    asm("cvt.rna.tf32.f32 %0, %1;" : "=r"(r) : "f"(x));
    return r;
}

__device__ __forceinline__ void mma_tf32(float* c, unsigned a0, unsigned a1,
                                         unsigned a2, unsigned a3,
                                         unsigned b0, unsigned b1) {
    asm("mma.sync.aligned.m16n8k8.row.col.f32.tf32.tf32.f32 "
        "{%0,%1,%2,%3},{%4,%5,%6,%7},{%8,%9},{%0,%1,%2,%3};"
        : "+f"(c[0]), "+f"(c[1]), "+f"(c[2]), "+f"(c[3])
        : "r"(a0), "r"(a1), "r"(a2), "r"(a3), "r"(b0), "r"(b1));
}

// ---------------- embedding ----------------
__global__ __launch_bounds__(256) void embed_kernel(
    const float* __restrict__ demo, const float* __restrict__ times,
    const float* __restrict__ values, const float* __restrict__ timescales,
    const float* __restrict__ W_demo, const float* __restrict__ b_demo,
    const float* __restrict__ W_val, const float* __restrict__ b_val,
    const int* __restrict__ length) {
    int idx = blockIdx.x * blockDim.x + threadIdx.x;
    if (idx >= BB * SS * DD) return;
    int d = idx % DD;
    int s = (idx / DD) % SS;
    int b = idx / (DD * SS);
    if (s > length[b]) return;  // masked everywhere downstream
    float out;
    if (s == 0) {
        float acc = b_demo[d];
        #pragma unroll
        for (int k = 0; k < NDEMO; k++) acc += demo[b * NDEMO + k] * W_demo[k * DD + d];
        out = acc;
    } else {
        int t = s - 1;
        float acc = b_val[d];
        const float4* vrow = (const float4*)(values + (b * LL + t) * DVAL);
        #pragma unroll
        for (int k4 = 0; k4 < DVAL / 4; k4++) {
            float4 vv = vrow[k4];
            acc += vv.x * W_val[(k4 * 4 + 0) * DD + d];
            acc += vv.y * W_val[(k4 * 4 + 1) * DD + d];
            acc += vv.z * W_val[(k4 * 4 + 2) * DD + d];
            acc += vv.w * W_val[(k4 * 4 + 3) * DD + d];
        }
        float tm = times[b * LL + t];
        float st = tm / timescales[d & 63];
        out = acc + ((d < 64) ? __sinf(st) : __cosf(st));
    }
    g_x[idx] = out;
}

// ---------------- fused QKV projection: 16 rows/block, k-unroll-4 ----------------
__global__ __launch_bounds__(128) void qkv_kernel(
    const int* __restrict__ length,
    const float* __restrict__ Wq, const float* __restrict__ bq,
    const float* __restrict__ Wk, const float* __restrict__ bk,
    const float* __restrict__ Wv, const float* __restrict__ bv) {
    int row0 = blockIdx.x * 16;
    int b = row0 >> 10;
    int valid_len = length[b] + 1;
    if ((row0 & (SS - 1)) >= valid_len) return;
    __shared__ float xs[16][DD];
    int t = threadIdx.x;
    #pragma unroll
    for (int r = 0; r < 16; r++) xs[r][t] = g_x[(row0 + r) * DD + t];
    __syncthreads();
    float aq[16], ak[16], av[16];
    float biq = bq[t], bik = bk[t], biv = bv[t];
    #pragma unroll
    for (int r = 0; r < 16; r++) { aq[r] = biq; ak[r] = bik; av[r] = biv; }
    for (int k = 0; k < DD; k += 4) {
        float wq0 = Wq[(k + 0) * DD + t], wq1 = Wq[(k + 1) * DD + t];
        float wq2 = Wq[(k + 2) * DD + t], wq3 = Wq[(k + 3) * DD + t];
        float wk0 = Wk[(k + 0) * DD + t], wk1 = Wk[(k + 1) * DD + t];
        float wk2 = Wk[(k + 2) * DD + t], wk3 = Wk[(k + 3) * DD + t];
        float wv0 = Wv[(k + 0) * DD + t], wv1 = Wv[(k + 1) * DD + t];
        float wv2 = Wv[(k + 2) * DD + t], wv3 = Wv[(k + 3) * DD + t];
        #pragma unroll
        for (int r = 0; r < 16; r++) {
            float4 x4 = *(const float4*)&xs[r][k];
            aq[r] += x4.x * wq0 + x4.y * wq1 + x4.z * wq2 + x4.w * wq3;
            ak[r] += x4.x * wk0 + x4.y * wk1 + x4.z * wk2 + x4.w * wk3;
            av[r] += x4.x * wv0 + x4.y * wv1 + x4.z * wv2 + x4.w * wv3;
        }
    }
    #pragma unroll
    for (int r = 0; r < 16; r++) {
        g_q[(row0 + r) * DD + t] = aq[r];
        g_k[(row0 + r) * DD + t] = ak[r];
        g_v[(row0 + r) * DD + t] = av[r];
    }
}

// ---------------- flash attention, tf32 mma: block = (64q, h, b), 4 warps ----------------
__global__ __launch_bounds__(128) void attn_mma_kernel(const int* __restrict__ length) {
    const int qt = blockIdx.x, h = blockIdx.y, b = blockIdx.z;
    int valid_len = length[b] + 1;
    int q0 = qt * 64;
    if (q0 >= valid_len) return;

    __shared__ unsigned Ks[16][40];   // [d][key], tf32 bits
    __shared__ unsigned Vs[32][24];   // [key][d], tf32 bits
    __shared__ unsigned Ps[64][36];   // [q][key], tf32 bits

    int t = threadIdx.x;
    int w = t >> 5, lane = t & 31;
    int g = lane >> 2, tg = lane & 3;
    int qrow_base = b * SS + q0 + w * 16;

    // Q fragments (A of QK^T), loaded once: 2 k8 steps covering d=16
    unsigned qa[2][4];
    #pragma unroll
    for (int ks = 0; ks < 2; ks++) {
        int r_lo = (qrow_base + g) * DD + h * DH + ks * 8 + tg;
        int r_hi = (qrow_base + g + 8) * DD + h * DH + ks * 8 + tg;
        qa[ks][0] = f2tf(g_q[r_lo]);
        qa[ks][1] = f2tf(g_q[r_hi]);
        qa[ks][2] = f2tf(g_q[r_lo + 4]);
        qa[ks][3] = f2tf(g_q[r_hi + 4]);
    }

    float m0 = -1e30f, m1 = -1e30f, l0 = 0.f, l1 = 0.f;
    float oc[2][4];
    #pragma unroll
    for (int i = 0; i < 2; i++)
        #pragma unroll
        for (int j = 0; j < 4; j++) oc[i][j] = 0.f;

    int nch = (valid_len + 31) >> 5;
    int key_ld = t >> 2, d4 = (t & 3) << 2;

    for (int c = 0; c < nch; c++) {
        __syncthreads();
        {
            int src = (b * SS + c * 32 + key_ld) * DD + h * DH + d4;
            float4 k4 = *(const float4*)(g_k + src);
            Ks[d4 + 0][key_ld] = f2tf(k4.x);
            Ks[d4 + 1][key_ld] = f2tf(k4.y);
            Ks[d4 + 2][key_ld] = f2tf(k4.z);
            Ks[d4 + 3][key_ld] = f2tf(k4.w);
            float4 v4 = *(const float4*)(g_v + src);
            uint4 vv = {f2tf(v4.x), f2tf(v4.y), f2tf(v4.z), f2tf(v4.w)};
            *(uint4*)&Vs[key_ld][d4] = vv;
        }
        __syncthreads();

        // S = Q K^T  (4 n8 key tiles)
        float sc[4][4];
        #pragma unroll
        for (int nt = 0; nt < 4; nt++) {
            sc[nt][0] = sc[nt][1] = sc[nt][2] = sc[nt][3] = 0.f;
            #pragma unroll
            for (int ks = 0; ks < 2; ks++) {
                unsigned b0 = Ks[ks * 8 + tg][nt * 8 + g];
                unsigned b1 = Ks[ks * 8 + tg + 4][nt * 8 + g];
                mma_tf32(sc[nt], qa[ks][0], qa[ks][1], qa[ks][2], qa[ks][3], b0, b1);
            }
        }

        // scale + mask + row max
        int limit = valid_len - c * 32;
        float rmax0 = -1e30f, rmax1 = -1e30f;
        #pragma unroll
        for (int nt = 0; nt < 4; nt++) {
            int col0 = nt * 8 + 2 * tg;
            int col1 = col0 + 1;
            sc[nt][0] = (col0 < limit) ? sc[nt][0] * 0.25f : -1e30f;
            sc[nt][1] = (col1 < limit) ? sc[nt][1] * 0.25f : -1e30f;
            sc[nt][2] = (col0 < limit) ? sc[nt][2] * 0.25f : -1e30f;
            sc[nt][3] = (col1 < limit) ? sc[nt][3] * 0.25f : -1e30f;
            rmax0 = fmaxf(rmax0, fmaxf(sc[nt][0], sc[nt][1]));
            rmax1 = fmaxf(rmax1, fmaxf(sc[nt][2], sc[nt][3]));
        }
        rmax0 = fmaxf(rmax0, __shfl_xor_sync(0xffffffff, rmax0, 1));
        rmax0 = fmaxf(rmax0, __shfl_xor_sync(0xffffffff, rmax0, 2));
        rmax1 = fmaxf(rmax1, __shfl_xor_sync(0xffffffff, rmax1, 1));
        rmax1 = fmaxf(rmax1, __shfl_xor_sync(0xffffffff, rmax1, 2));

        float mn0 = fmaxf(m0, rmax0), mn1 = fmaxf(m1, rmax1);
        float scale0 = __expf(m0 - mn0), scale1 = __expf(m1 - mn1);

        float ls0 = 0.f, ls1 = 0.f;
        #pragma unroll
        for (int nt = 0; nt < 4; nt++) {
            float p0 = __expf(sc[nt][0] - mn0);
            float p1 = __expf(sc[nt][1] - mn0);
            float p2 = __expf(sc[nt][2] - mn1);
            float p3 = __expf(sc[nt][3] - mn1);
            ls0 += p0 + p1;
            ls1 += p2 + p3;
            int colw = nt * 8 + 2 * tg;
            uint2 lo = {f2tf(p0), f2tf(p1)};
            uint2 hi = {f2tf(p2), f2tf(p3)};
            *(uint2*)&Ps[w * 16 + g][colw] = lo;
            *(uint2*)&Ps[w * 16 + g + 8][colw] = hi;
        }
        ls0 += __shfl_xor_sync(0xffffffff, ls0, 1);
        ls0 += __shfl_xor_sync(0xffffffff, ls0, 2);
        ls1 += __shfl_xor_sync(0xffffffff, ls1, 1);
        ls1 += __shfl_xor_sync(0xffffffff, ls1, 2);
        l0 = l0 * scale0 + ls0;
        l1 = l1 * scale1 + ls1;
        #pragma unroll
        for (int mt = 0; mt < 2; mt++) {
            oc[mt][0] *= scale0; oc[mt][1] *= scale0;
            oc[mt][2] *= scale1; oc[mt][3] *= scale1;
        }
        m0 = mn0; m1 = mn1;
        __syncwarp();

        // O += P V  (k over 32 keys = 4 k8 steps, 2 n8 d tiles)
        #pragma unroll
        for (int j = 0; j < 4; j++) {
            unsigned pa0 = Ps[w * 16 + g][j * 8 + tg];
            unsigned pa1 = Ps[w * 16 + g + 8][j * 8 + tg];
            unsigned pa2 = Ps[w * 16 + g][j * 8 + tg + 4];
            unsigned pa3 = Ps[w * 16 + g + 8][j * 8 + tg + 4];
            #pragma unroll
            for (int mt = 0; mt < 2; mt++) {
                unsigned vb0 = Vs[j * 8 + tg][mt * 8 + g];
                unsigned vb1 = Vs[j * 8 + tg + 4][mt * 8 + g];
                mma_tf32(oc[mt], pa0, pa1, pa2, pa3, vb0, vb1);
            }
        }
    }

    float inv0 = 1.f / l0, inv1 = 1.f / l1;
    #pragma unroll
    for (int mt = 0; mt < 2; mt++) {
        int col = h * DH + mt * 8 + 2 * tg;
        float2 lo = {oc[mt][0] * inv0, oc[mt][1] * inv0};
        float2 hi = {oc[mt][2] * inv1, oc[mt][3] * inv1};
        *(float2*)&g_o[(qrow_base + g) * DD + col] = lo;
        *(float2*)&g_o[(qrow_base + g + 8) * DD + col] = hi;
    }
}

// ---------------- O-proj + residual + LN1: 16 rows/block ----------------
__global__ __launch_bounds__(128) void oproj_ln_kernel(
    const int* __restrict__ length,
    const float* __restrict__ Wo, const float* __restrict__ bo,
    const float* __restrict__ g1, const float* __restrict__ be1) {
    int row0 = blockIdx.x * 16;
    int b = row0 >> 10;
    int valid_len = length[b] + 1;
    if ((row0 & (SS - 1)) >= valid_len) return;
    __shared__ float os[16][DD];
    __shared__ float ys[16][DD];
    __shared__ float mean_s[16], rstd_s[16];
    int t = threadIdx.x;
    #pragma unroll
    for (int r = 0; r < 16; r++) os[r][t] = g_o[(row0 + r) * DD + t];
    __syncthreads();
    float acc[16];
    float bias = bo[t];
    #pragma unroll
    for (int r = 0; r < 16; r++) acc[r] = bias;
    for (int k = 0; k < DD; k += 4) {
        float w0 = Wo[(k + 0) * DD + t], w1 = Wo[(k + 1) * DD + t];
        float w2 = Wo[(k + 2) * DD + t], w3 = Wo[(k + 3) * DD + t];
        #pragma unroll
        for (int r = 0; r < 16; r++) {
            float4 x4 = *(const float4*)&os[r][k];
            acc[r] += x4.x * w0 + x4.y * w1 + x4.z * w2 + x4.w * w3;
        }
    }
    #pragma unroll
    for (int r = 0; r < 16; r++) ys[r][t] = acc[r] + g_x[(row0 + r) * DD + t];
    __syncthreads();
    int lane = t & 31, w = t >> 5;
    #pragma unroll
    for (int i = 0; i < 4; i++) {
        int r = (i << 2) | w;
        float s1 = 0.f, s2 = 0.f;
        #pragma unroll
        for (int j = 0; j < 4; j++) {
            float v = ys[r][lane + 32 * j];
            s1 += v; s2 += v * v;
        }
        #pragma unroll
        for (int o = 16; o > 0; o >>= 1) {
            s1 += __shfl_xor_sync(0xffffffff, s1, o);
            s2 += __shfl_xor_sync(0xffffffff, s2, o);
        }
        if (lane == 0) {
            float mu = s1 * (1.f / DD);
            float var = fmaxf(s2 * (1.f / DD) - mu * mu, 0.f);
            mean_s[r] = mu;
            rstd_s[r] = rsqrtf(var + 1e-3f);
        }
    }
    __syncthreads();
    float g = g1[t], bb = be1[t];
    #pragma unroll
    for (int r = 0; r < 16; r++)
        g_x[(row0 + r) * DD + t] = (ys[r][t] - mean_s[r]) * rstd_s[r] * g + bb;
}

// ---------------- FFN + residual + LN2: 8 rows/block, 256 threads ----------------
__global__ __launch_bounds__(256) void ffn_kernel(
    const int* __restrict__ length,
    const float* __restrict__ W1, const float* __restrict__ b1,
    const float* __restrict__ W2, const float* __restrict__ b2,
    const float* __restrict__ g2, const float* __restrict__ be2) {
    int row0 = blockIdx.x * 8;
    int b = row0 >> 10;
    int valid_len = length[b] + 1;
    if ((row0 & (SS - 1)) >= valid_len) return;
    __shared__ float xs[8][DD];
    __shared__ float hs[8][DFF];
    __shared__ float ys[8][DD];
    __shared__ float mean_s[8], rstd_s[8];
    int t = threadIdx.x;

    {
        const float4* src = (const float4*)(g_x + row0 * DD);
        if (t < 8 * DD / 4) ((float4*)(&xs[0][0]))[t] = src[t];
    }
    __syncthreads();

    {
        float a0[8], a1[8];
        float bi0 = b1[t], bi1 = b1[t + 256];
        #pragma unroll
        for (int r = 0; r < 8; r++) { a0[r] = bi0; a1[r] = bi1; }
        for (int k = 0; k < DD; k += 4) {
            float u0 = W1[(k + 0) * DFF + t], u1 = W1[(k + 1) * DFF + t];
            float u2 = W1[(k + 2) * DFF + t], u3 = W1[(k + 3) * DFF + t];
            float v0 = W1[(k + 0) * DFF + t + 256], v1 = W1[(k + 1) * DFF + t + 256];
            float v2 = W1[(k + 2) * DFF + t + 256], v3 = W1[(k + 3) * DFF + t + 256];
            #pragma unroll
            for (int r = 0; r < 8; r++) {
                float4 x4 = *(const float4*)&xs[r][k];
                a0[r] += x4.x * u0 + x4.y * u1 + x4.z * u2 + x4.w * u3;
                a1[r] += x4.x * v0 + x4.y * v1 + x4.z * v2 + x4.w * v3;
            }
        }
        #pragma unroll
        for (int r = 0; r < 8; r++) {
            hs[r][t] = fmaxf(a0[r], 0.f);
            hs[r][t + 256] = fmaxf(a1[r], 0.f);
        }
    }
    __syncthreads();

    {
        int d = t & 127, rg = t >> 7;
        float acc[4];
        float bias = b2[d];
        #pragma unroll
        for (int i = 0; i < 4; i++) acc[i] = bias;
        for (int j = 0; j < DFF; j += 4) {
            float w0 = W2[(j + 0) * DD + d], w1 = W2[(j + 1) * DD + d];
            float w2 = W2[(j + 2) * DD + d], w3 = W2[(j + 3) * DD + d];
            #pragma unroll
            for (int i = 0; i < 4; i++) {
                float4 h4 = *(const float4*)&hs[rg * 4 + i][j];
                acc[i] += h4.x * w0 + h4.y * w1 + h4.z * w2 + h4.w * w3;
            }
        }
        #pragma unroll
        for (int i = 0; i < 4; i++) {
            int r = rg * 4 + i;
            ys[r][d] = acc[i] + xs[r][d];
        }
    }
    __syncthreads();

    {
        int lane = t & 31, w = t >> 5;
        float s1 = 0.f, s2 = 0.f;
        #pragma unroll
        for (int j = 0; j < 4; j++) {
            float v = ys[w][lane + 32 * j];
            s1 += v; s2 += v * v;
        }
        #pragma unroll
        for (int o = 16; o > 0; o >>= 1) {
            s1 += __shfl_xor_sync(0xffffffff, s1, o);
            s2 += __shfl_xor_sync(0xffffffff, s2, o);
        }
        if (lane == 0) {
            float mu = s1 * (1.f / DD);
            float var = fmaxf(s2 * (1.f / DD) - mu * mu, 0.f);
            mean_s[w] = mu;
            rstd_s[w] = rsqrtf(var + 1e-3f);
        }
    }
    __syncthreads();
    {
        int d = t & 127, rg = t >> 7;
        float g = g2[d], bb = be2[d];
        #pragma unroll
        for (int i = 0; i < 4; i++) {
            int r = rg * 4 + i;
            g_x[(row0 + r) * DD + d] = (ys[r][d] - mean_s[r]) * rstd_s[r] * g + bb;
        }
    }
}

// ---------------- masked mean-pool + MLP head + sigmoid ----------------
__global__ __launch_bounds__(256) void head_kernel(
    const int* __restrict__ length,
    const float* __restrict__ Wm1, const float* __restrict__ bm1,
    const float* __restrict__ Wm2, const float* __restrict__ bm2,
    float* __restrict__ out) {
    int b = blockIdx.x;
    int t = threadIdx.x;
    __shared__ float part[2][DD];
    __shared__ float agg[DD];
    __shared__ float hh[MLPH];
    __shared__ float red[8];
    int cnt = length[b] + 1;
    int d = t & 127, grp = t >> 7;
    float s0 = 0.f, s1 = 0.f, s2 = 0.f, s3 = 0.f;
    int ss = grp;
    for (; ss + 6 < cnt; ss += 8) {
        s0 += g_x[(b * SS + ss) * DD + d];
        s1 += g_x[(b * SS + ss + 2) * DD + d];
        s2 += g_x[(b * SS + ss + 4) * DD + d];
        s3 += g_x[(b * SS + ss + 6) * DD + d];
    }
    for (; ss < cnt; ss += 2) s0 += g_x[(b * SS + ss) * DD + d];
    part[grp][d] = s0 + s1 + s2 + s3;
    __syncthreads();
    if (t < DD) agg[t] = (part[0][t] + part[1][t]) / (float)cnt;
    __syncthreads();
    {
        float acc = bm1[t];
        #pragma unroll 8
        for (int k = 0; k < DD; k++) acc += agg[k] * Wm1[k * MLPH + t];
        hh[t] = fmaxf(acc, 0.f);
    }
    __syncthreads();
    float v = hh[t] * Wm2[t];
    #pragma unroll
    for (int o = 16; o > 0; o >>= 1) v += __shfl_xor_sync(0xffffffff, v, o);
    if ((t & 31) == 0) red[t >> 5] = v;
    __syncthreads();
    if (t == 0) {
        float s = 0.f;
        #pragma unroll
        for (int i = 0; i < 8; i++) s += red[i];
        s += bm2[0];
        out[b] = 1.f / (1.f + __expf(-s));
    }
}

// ---------------- launch ----------------
extern "C" void kernel_launch(void* const* d_in, const int* in_sizes, int n_in,
                              void* d_out, int out_size) {
    (void)in_sizes; (void)n_in; (void)out_size;
    const float* demo       = (const float*)d_in[0];
    const float* times      = (const float*)d_in[1];
    const float* values     = (const float*)d_in[2];
    const int*   length     = (const int*)d_in[3];
    const float* timescales = (const float*)d_in[4];
    const float* W_demo = (const float*)d_in[5];
    const float* b_demo = (const float*)d_in[6];
    const float* W_val  = (const float*)d_in[7];
    const float* b_val  = (const float*)d_in[8];
    const float* Wq = (const float*)d_in[9];
    const float* bq = (const float*)d_in[10];
    const float* Wk = (const float*)d_in[11];
    const float* bk = (const float*)d_in[12];
    const float* Wv = (const float*)d_in[13];
    const float* bv = (const float*)d_in[14];
    const float* Wo = (const float*)d_in[15];
    const float* bo = (const float*)d_in[16];
    const float* ln1g = (const float*)d_in[17];
    const float* ln1b = (const float*)d_in[18];
    const float* W1 = (const float*)d_in[19];
    const float* b1 = (const float*)d_in[20];
    const float* W2 = (const float*)d_in[21];
    const float* b2 = (const float*)d_in[22];
    const float* ln2g = (const float*)d_in[23];
    const float* ln2b = (const float*)d_in[24];
    const float* Wm1 = (const float*)d_in[25];
    const float* bm1 = (const float*)d_in[26];
    const float* Wm2 = (const float*)d_in[27];
    const float* bm2 = (const float*)d_in[28];
    float* out = (float*)d_out;

    embed_kernel<<<(BB * SS * DD + 255) / 256, 256>>>(
        demo, times, values, timescales, W_demo, b_demo, W_val, b_val, length);

    for (int l = 0; l < NLAY; l++) {
        qkv_kernel<<<BB * SS / 16, 128>>>(length,
            Wq + l * DD * DD, bq + l * DD,
            Wk + l * DD * DD, bk + l * DD,
            Wv + l * DD * DD, bv + l * DD);
        dim3 ag(SS / 64, HH, BB);
        attn_mma_kernel<<<ag, 128>>>(length);
        oproj_ln_kernel<<<BB * SS / 16, 128>>>(length,
            Wo + l * DD * DD, bo + l * DD, ln1g + l * DD, ln1b + l * DD);
        ffn_kernel<<<BB * SS / 8, 256>>>(length,
            W1 + l * DD * DFF, b1 + l * DFF,
            W2 + l * DFF * DD, b2 + l * DD,
            ln2g + l * DD, ln2b + l * DD);
    }

    head_kernel<<<BB, 256>>>(length, Wm1, bm1, Wm2, bm2, out);
}

// round 5
// speedup vs baseline: 5.7087x; 1.4428x over previous
#include <cuda_runtime.h>
#include <math.h>

#define BB 16
#define LL 1023
#define SS 1024
#define DD 128
#define DVAL 64
#define NDEMO 16
#define HH 8
#define DH 16
#define NLAY 2
#define DFF 512
#define MLPH 256

// ---------------- device scratch (no allocs allowed) ----------------
__device__ float g_x[BB * SS * DD];
__device__ float g_q[BB * SS * DD];
__device__ float g_k[BB * SS * DD];
__device__ float g_v[BB * SS * DD];
__device__ float g_o[BB * SS * DD];
__device__ float g_h[BB * SS * DFF];

__device__ __forceinline__ unsigned f2tf(float x) {
    unsigned r;
    asm("cvt.rna.tf32.f32 %0, %1;" : "=r"(r) : "f"(x));
    return r;
}

__device__ __forceinline__ void mma_tf32(float* c, unsigned a0, unsigned a1,
                                         unsigned a2, unsigned a3,
                                         unsigned b0, unsigned b1) {
    asm("mma.sync.aligned.m16n8k8.row.col.f32.tf32.tf32.f32 "
        "{%0,%1,%2,%3},{%4,%5,%6,%7},{%8,%9},{%0,%1,%2,%3};"
        : "+f"(c[0]), "+f"(c[1]), "+f"(c[2]), "+f"(c[3])
        : "r"(a0), "r"(a1), "r"(a2), "r"(a3), "r"(b0), "r"(b1));
}

// ---------------- GEMM tile helpers: 64 rows x 128 cols, 256 threads ----------------
// As[64][36]: 64 rows x 32 k; Bs[32][136]: 32 k x 128 n. Strides chosen so
// frag reads (4g+tg) and (8tg+g) are bank-conflict-free.
__device__ __forceinline__ void stage_As(unsigned (*As)[36], const float* Ag,
                                         int lda, int t) {
    int r = t >> 2, c0 = (t & 3) * 8;
    const float4* s = (const float4*)(Ag + (size_t)r * lda + c0);
    float4 v0 = s[0], v1 = s[1];
    As[r][c0 + 0] = f2tf(v0.x); As[r][c0 + 1] = f2tf(v0.y);
    As[r][c0 + 2] = f2tf(v0.z); As[r][c0 + 3] = f2tf(v0.w);
    As[r][c0 + 4] = f2tf(v1.x); As[r][c0 + 5] = f2tf(v1.y);
    As[r][c0 + 6] = f2tf(v1.z); As[r][c0 + 7] = f2tf(v1.w);
}

__device__ __forceinline__ void stage_Bs(unsigned (*Bs)[136], const float* Wg,
                                         int ldw, int t) {
    int r = t >> 3, f0 = t & 7;
    #pragma unroll
    for (int j = 0; j < 4; j++) {
        int c = (f0 + j * 8) * 4;
        float4 v = *(const float4*)(Wg + (size_t)r * ldw + c);
        Bs[r][c + 0] = f2tf(v.x); Bs[r][c + 1] = f2tf(v.y);
        Bs[r][c + 2] = f2tf(v.z); Bs[r][c + 3] = f2tf(v.w);
    }
}

__device__ __forceinline__ void compute_chunk(float (*acc)[4],
                                              const unsigned (*As)[36],
                                              const unsigned (*Bs)[136],
                                              int mq, int nh, int g, int tg) {
    int mr = mq * 16;
    #pragma unroll
    for (int ks = 0; ks < 4; ks++) {
        unsigned a0 = As[mr + g][ks * 8 + tg];
        unsigned a1 = As[mr + g + 8][ks * 8 + tg];
        unsigned a2 = As[mr + g][ks * 8 + tg + 4];
        unsigned a3 = As[mr + g + 8][ks * 8 + tg + 4];
        #pragma unroll
        for (int nt = 0; nt < 8; nt++) {
            unsigned b0 = Bs[ks * 8 + tg][nh * 64 + nt * 8 + g];
            unsigned b1 = Bs[ks * 8 + tg + 4][nh * 64 + nt * 8 + g];
            mma_tf32(acc[nt], a0, a1, a2, a3, b0, b1);
        }
    }
}

// ---------------- embedding ----------------
__global__ __launch_bounds__(256) void embed_kernel(
    const float* __restrict__ demo, const float* __restrict__ times,
    const float* __restrict__ values, const float* __restrict__ timescales,
    const float* __restrict__ W_demo, const float* __restrict__ b_demo,
    const float* __restrict__ W_val, const float* __restrict__ b_val,
    const int* __restrict__ length) {
    int idx = blockIdx.x * blockDim.x + threadIdx.x;
    if (idx >= BB * SS * DD) return;
    int d = idx % DD;
    int s = (idx / DD) % SS;
    int b = idx / (DD * SS);
    if (s > length[b]) return;
    float out;
    if (s == 0) {
        float acc = b_demo[d];
        #pragma unroll
        for (int k = 0; k < NDEMO; k++) acc += demo[b * NDEMO + k] * W_demo[k * DD + d];
        out = acc;
    } else {
        int t = s - 1;
        float acc = b_val[d];
        const float4* vrow = (const float4*)(values + (b * LL + t) * DVAL);
        #pragma unroll
        for (int k4 = 0; k4 < DVAL / 4; k4++) {
            float4 vv = vrow[k4];
            acc += vv.x * W_val[(k4 * 4 + 0) * DD + d];
            acc += vv.y * W_val[(k4 * 4 + 1) * DD + d];
            acc += vv.z * W_val[(k4 * 4 + 2) * DD + d];
            acc += vv.w * W_val[(k4 * 4 + 3) * DD + d];
        }
        float tm = times[b * LL + t];
        float st = tm / timescales[d & 63];
        out = acc + ((d < 64) ? __sinf(st) : __cosf(st));
    }
    g_x[idx] = out;
}

// ---------------- QKV: grid (tiles, 3), tf32 mma ----------------
__global__ __launch_bounds__(256) void qkv_mma_kernel(
    const int* __restrict__ length,
    const float* __restrict__ Wq, const float* __restrict__ bq,
    const float* __restrict__ Wk, const float* __restrict__ bk,
    const float* __restrict__ Wv, const float* __restrict__ bv) {
    int row0 = blockIdx.x * 64;
    int b = row0 >> 10;
    int valid_len = length[b] + 1;
    if ((row0 & (SS - 1)) >= valid_len) return;
    int wi = blockIdx.y;
    const float* W = (wi == 0) ? Wq : (wi == 1) ? Wk : Wv;
    const float* bias = (wi == 0) ? bq : (wi == 1) ? bk : bv;
    float* out = (wi == 0) ? g_q : (wi == 1) ? g_k : g_v;

    __shared__ unsigned As[64][36];
    __shared__ unsigned Bs[32][136];
    int t = threadIdx.x, w = t >> 5, lane = t & 31;
    int g = lane >> 2, tg = lane & 3, mq = w >> 1, nh = w & 1;

    float acc[8][4];
    #pragma unroll
    for (int i = 0; i < 8; i++) acc[i][0] = acc[i][1] = acc[i][2] = acc[i][3] = 0.f;

    #pragma unroll
    for (int kc = 0; kc < 4; kc++) {
        __syncthreads();
        stage_As(As, g_x + (size_t)row0 * DD + kc * 32, DD, t);
        stage_Bs(Bs, W + (size_t)(kc * 32) * DD, DD, t);
        __syncthreads();
        compute_chunk(acc, As, Bs, mq, nh, g, tg);
    }

    int r0 = row0 + mq * 16 + g, r1 = r0 + 8;
    #pragma unroll
    for (int nt = 0; nt < 8; nt++) {
        int col = nh * 64 + nt * 8 + 2 * tg;
        float2 bi = *(const float2*)&bias[col];
        float2 lo = {acc[nt][0] + bi.x, acc[nt][1] + bi.y};
        float2 hi = {acc[nt][2] + bi.x, acc[nt][3] + bi.y};
        *(float2*)&out[(size_t)r0 * DD + col] = lo;
        *(float2*)&out[(size_t)r1 * DD + col] = hi;
    }
}

// ---------------- flash attention, tf32 mma (unchanged from R4) ----------------
__global__ __launch_bounds__(128) void attn_mma_kernel(const int* __restrict__ length) {
    const int qt = blockIdx.x, h = blockIdx.y, b = blockIdx.z;
    int valid_len = length[b] + 1;
    int q0 = qt * 64;
    if (q0 >= valid_len) return;

    __shared__ unsigned Ks[16][40];
    __shared__ unsigned Vs[32][24];
    __shared__ unsigned Ps[64][36];

    int t = threadIdx.x;
    int w = t >> 5, lane = t & 31;
    int g = lane >> 2, tg = lane & 3;
    int qrow_base = b * SS + q0 + w * 16;

    unsigned qa[2][4];
    #pragma unroll
    for (int ks = 0; ks < 2; ks++) {
        int r_lo = (qrow_base + g) * DD + h * DH + ks * 8 + tg;
        int r_hi = (qrow_base + g + 8) * DD + h * DH + ks * 8 + tg;
        qa[ks][0] = f2tf(g_q[r_lo]);
        qa[ks][1] = f2tf(g_q[r_hi]);
        qa[ks][2] = f2tf(g_q[r_lo + 4]);
        qa[ks][3] = f2tf(g_q[r_hi + 4]);
    }

    float m0 = -1e30f, m1 = -1e30f, l0 = 0.f, l1 = 0.f;
    float oc[2][4];
    #pragma unroll
    for (int i = 0; i < 2; i++)
        #pragma unroll
        for (int j = 0; j < 4; j++) oc[i][j] = 0.f;

    int nch = (valid_len + 31) >> 5;
    int key_ld = t >> 2, d4 = (t & 3) << 2;

    for (int c = 0; c < nch; c++) {
        __syncthreads();
        {
            int src = (b * SS + c * 32 + key_ld) * DD + h * DH + d4;
            float4 k4 = *(const float4*)(g_k + src);
            Ks[d4 + 0][key_ld] = f2tf(k4.x);
            Ks[d4 + 1][key_ld] = f2tf(k4.y);
            Ks[d4 + 2][key_ld] = f2tf(k4.z);
            Ks[d4 + 3][key_ld] = f2tf(k4.w);
            float4 v4 = *(const float4*)(g_v + src);
            uint4 vv = {f2tf(v4.x), f2tf(v4.y), f2tf(v4.z), f2tf(v4.w)};
            *(uint4*)&Vs[key_ld][d4] = vv;
        }
        __syncthreads();

        float sc[4][4];
        #pragma unroll
        for (int nt = 0; nt < 4; nt++) {
            sc[nt][0] = sc[nt][1] = sc[nt][2] = sc[nt][3] = 0.f;
            #pragma unroll
            for (int ks = 0; ks < 2; ks++) {
                unsigned b0 = Ks[ks * 8 + tg][nt * 8 + g];
                unsigned b1 = Ks[ks * 8 + tg + 4][nt * 8 + g];
                mma_tf32(sc[nt], qa[ks][0], qa[ks][1], qa[ks][2], qa[ks][3], b0, b1);
            }
        }

        int limit = valid_len - c * 32;
        float rmax0 = -1e30f, rmax1 = -1e30f;
        #pragma unroll
        for (int nt = 0; nt < 4; nt++) {
            int col0 = nt * 8 + 2 * tg;
            int col1 = col0 + 1;
            sc[nt][0] = (col0 < limit) ? sc[nt][0] * 0.25f : -1e30f;
            sc[nt][1] = (col1 < limit) ? sc[nt][1] * 0.25f : -1e30f;
            sc[nt][2] = (col0 < limit) ? sc[nt][2] * 0.25f : -1e30f;
            sc[nt][3] = (col1 < limit) ? sc[nt][3] * 0.25f : -1e30f;
            rmax0 = fmaxf(rmax0, fmaxf(sc[nt][0], sc[nt][1]));
            rmax1 = fmaxf(rmax1, fmaxf(sc[nt][2], sc[nt][3]));
        }
        rmax0 = fmaxf(rmax0, __shfl_xor_sync(0xffffffff, rmax0, 1));
        rmax0 = fmaxf(rmax0, __shfl_xor_sync(0xffffffff, rmax0, 2));
        rmax1 = fmaxf(rmax1, __shfl_xor_sync(0xffffffff, rmax1, 1));
        rmax1 = fmaxf(rmax1, __shfl_xor_sync(0xffffffff, rmax1, 2));

        float mn0 = fmaxf(m0, rmax0), mn1 = fmaxf(m1, rmax1);
        float scale0 = __expf(m0 - mn0), scale1 = __expf(m1 - mn1);

        float ls0 = 0.f, ls1 = 0.f;
        #pragma unroll
        for (int nt = 0; nt < 4; nt++) {
            float p0 = __expf(sc[nt][0] - mn0);
            float p1 = __expf(sc[nt][1] - mn0);
            float p2 = __expf(sc[nt][2] - mn1);
            float p3 = __expf(sc[nt][3] - mn1);
            ls0 += p0 + p1;
            ls1 += p2 + p3;
            int colw = nt * 8 + 2 * tg;
            uint2 lo = {f2tf(p0), f2tf(p1)};
            uint2 hi = {f2tf(p2), f2tf(p3)};
            *(uint2*)&Ps[w * 16 + g][colw] = lo;
            *(uint2*)&Ps[w * 16 + g + 8][colw] = hi;
        }
        ls0 += __shfl_xor_sync(0xffffffff, ls0, 1);
        ls0 += __shfl_xor_sync(0xffffffff, ls0, 2);
        ls1 += __shfl_xor_sync(0xffffffff, ls1, 1);
        ls1 += __shfl_xor_sync(0xffffffff, ls1, 2);
        l0 = l0 * scale0 + ls0;
        l1 = l1 * scale1 + ls1;
        #pragma unroll
        for (int mt = 0; mt < 2; mt++) {
            oc[mt][0] *= scale0; oc[mt][1] *= scale0;
            oc[mt][2] *= scale1; oc[mt][3] *= scale1;
        }
        m0 = mn0; m1 = mn1;
        __syncwarp();

        #pragma unroll
        for (int j = 0; j < 4; j++) {
            unsigned pa0 = Ps[w * 16 + g][j * 8 + tg];
            unsigned pa1 = Ps[w * 16 + g + 8][j * 8 + tg];
            unsigned pa2 = Ps[w * 16 + g][j * 8 + tg + 4];
            unsigned pa3 = Ps[w * 16 + g + 8][j * 8 + tg + 4];
            #pragma unroll
            for (int mt = 0; mt < 2; mt++) {
                unsigned vb0 = Vs[j * 8 + tg][mt * 8 + g];
                unsigned vb1 = Vs[j * 8 + tg + 4][mt * 8 + g];
                mma_tf32(oc[mt], pa0, pa1, pa2, pa3, vb0, vb1);
            }
        }
    }

    float inv0 = 1.f / l0, inv1 = 1.f / l1;
    #pragma unroll
    for (int mt = 0; mt < 2; mt++) {
        int col = h * DH + mt * 8 + 2 * tg;
        float2 lo = {oc[mt][0] * inv0, oc[mt][1] * inv0};
        float2 hi = {oc[mt][2] * inv1, oc[mt][3] * inv1};
        *(float2*)&g_o[(qrow_base + g) * DD + col] = lo;
        *(float2*)&g_o[(qrow_base + g + 8) * DD + col] = hi;
    }
}

// ---------------- O-proj + residual + LN1, tf32 mma ----------------
__global__ __launch_bounds__(256) void oproj_ln_mma_kernel(
    const int* __restrict__ length,
    const float* __restrict__ Wo, const float* __restrict__ bo,
    const float* __restrict__ g1, const float* __restrict__ be1) {
    int row0 = blockIdx.x * 64;
    int b = row0 >> 10;
    int valid_len = length[b] + 1;
    if ((row0 & (SS - 1)) >= valid_len) return;

    __shared__ unsigned As[64][36];
    __shared__ unsigned Bs[32][136];
    __shared__ float redS[2][64];
    __shared__ float redQ[2][64];
    int t = threadIdx.x, w = t >> 5, lane = t & 31;
    int g = lane >> 2, tg = lane & 3, mq = w >> 1, nh = w & 1;

    float acc[8][4];
    #pragma unroll
    for (int i = 0; i < 8; i++) acc[i][0] = acc[i][1] = acc[i][2] = acc[i][3] = 0.f;

    #pragma unroll
    for (int kc = 0; kc < 4; kc++) {
        __syncthreads();
        stage_As(As, g_o + (size_t)row0 * DD + kc * 32, DD, t);
        stage_Bs(Bs, Wo + (size_t)(kc * 32) * DD, DD, t);
        __syncthreads();
        compute_chunk(acc, As, Bs, mq, nh, g, tg);
    }

    int r0 = row0 + mq * 16 + g, r1 = r0 + 8;
    float rs0 = 0.f, rq0 = 0.f, rs1 = 0.f, rq1 = 0.f;
    #pragma unroll
    for (int nt = 0; nt < 8; nt++) {
        int col = nh * 64 + nt * 8 + 2 * tg;
        float2 bi = *(const float2*)&bo[col];
        float2 e0 = *(const float2*)&g_x[(size_t)r0 * DD + col];
        float2 e1 = *(const float2*)&g_x[(size_t)r1 * DD + col];
        acc[nt][0] += bi.x + e0.x;
        acc[nt][1] += bi.y + e0.y;
        acc[nt][2] += bi.x + e1.x;
        acc[nt][3] += bi.y + e1.y;
        rs0 += acc[nt][0] + acc[nt][1];
        rq0 += acc[nt][0] * acc[nt][0] + acc[nt][1] * acc[nt][1];
        rs1 += acc[nt][2] + acc[nt][3];
        rq1 += acc[nt][2] * acc[nt][2] + acc[nt][3] * acc[nt][3];
    }
    rs0 += __shfl_xor_sync(0xffffffff, rs0, 1);
    rs0 += __shfl_xor_sync(0xffffffff, rs0, 2);
    rq0 += __shfl_xor_sync(0xffffffff, rq0, 1);
    rq0 += __shfl_xor_sync(0xffffffff, rq0, 2);
    rs1 += __shfl_xor_sync(0xffffffff, rs1, 1);
    rs1 += __shfl_xor_sync(0xffffffff, rs1, 2);
    rq1 += __shfl_xor_sync(0xffffffff, rq1, 1);
    rq1 += __shfl_xor_sync(0xffffffff, rq1, 2);
    if (tg == 0) {
        redS[nh][mq * 16 + g] = rs0;
        redS[nh][mq * 16 + g + 8] = rs1;
        redQ[nh][mq * 16 + g] = rq0;
        redQ[nh][mq * 16 + g + 8] = rq1;
    }
    __syncthreads();
    float mu0 = (redS[0][mq * 16 + g] + redS[1][mq * 16 + g]) * (1.f / DD);
    float mu1 = (redS[0][mq * 16 + g + 8] + redS[1][mq * 16 + g + 8]) * (1.f / DD);
    float v0 = fmaxf((redQ[0][mq * 16 + g] + redQ[1][mq * 16 + g]) * (1.f / DD) - mu0 * mu0, 0.f);
    float v1 = fmaxf((redQ[0][mq * 16 + g + 8] + redQ[1][mq * 16 + g + 8]) * (1.f / DD) - mu1 * mu1, 0.f);
    float rst0 = rsqrtf(v0 + 1e-3f), rst1 = rsqrtf(v1 + 1e-3f);
    #pragma unroll
    for (int nt = 0; nt < 8; nt++) {
        int col = nh * 64 + nt * 8 + 2 * tg;
        float2 gm = *(const float2*)&g1[col];
        float2 bt = *(const float2*)&be1[col];
        float2 lo = {(acc[nt][0] - mu0) * rst0 * gm.x + bt.x,
                     (acc[nt][1] - mu0) * rst0 * gm.y + bt.y};
        float2 hi = {(acc[nt][2] - mu1) * rst1 * gm.x + bt.x,
                     (acc[nt][3] - mu1) * rst1 * gm.y + bt.y};
        *(float2*)&g_x[(size_t)r0 * DD + col] = lo;
        *(float2*)&g_x[(size_t)r1 * DD + col] = hi;
    }
}

// ---------------- FFN1: x@W1+b1, relu -> g_h, grid (tiles, 4) ----------------
__global__ __launch_bounds__(256) void ffn1_mma_kernel(
    const int* __restrict__ length,
    const float* __restrict__ W1, const float* __restrict__ b1) {
    int row0 = blockIdx.x * 64;
    int b = row0 >> 10;
    int valid_len = length[b] + 1;
    if ((row0 & (SS - 1)) >= valid_len) return;
    int ncol0 = blockIdx.y * 128;

    __shared__ unsigned As[64][36];
    __shared__ unsigned Bs[32][136];
    int t = threadIdx.x, w = t >> 5, lane = t & 31;
    int g = lane >> 2, tg = lane & 3, mq = w >> 1, nh = w & 1;

    float acc[8][4];
    #pragma unroll
    for (int i = 0; i < 8; i++) acc[i][0] = acc[i][1] = acc[i][2] = acc[i][3] = 0.f;

    #pragma unroll
    for (int kc = 0; kc < 4; kc++) {
        __syncthreads();
        stage_As(As, g_x + (size_t)row0 * DD + kc * 32, DD, t);
        stage_Bs(Bs, W1 + (size_t)(kc * 32) * DFF + ncol0, DFF, t);
        __syncthreads();
        compute_chunk(acc, As, Bs, mq, nh, g, tg);
    }

    int r0 = row0 + mq * 16 + g, r1 = r0 + 8;
    #pragma unroll
    for (int nt = 0; nt < 8; nt++) {
        int col = ncol0 + nh * 64 + nt * 8 + 2 * tg;
        float2 bi = *(const float2*)&b1[col];
        float2 lo = {fmaxf(acc[nt][0] + bi.x, 0.f), fmaxf(acc[nt][1] + bi.y, 0.f)};
        float2 hi = {fmaxf(acc[nt][2] + bi.x, 0.f), fmaxf(acc[nt][3] + bi.y, 0.f)};
        *(float2*)&g_h[(size_t)r0 * DFF + col] = lo;
        *(float2*)&g_h[(size_t)r1 * DFF + col] = hi;
    }
}

// ---------------- FFN2 + residual + LN2, tf32 mma ----------------
__global__ __launch_bounds__(256) void ffn2_ln_mma_kernel(
    const int* __restrict__ length,
    const float* __restrict__ W2, const float* __restrict__ b2,
    const float* __restrict__ g2, const float* __restrict__ be2) {
    int row0 = blockIdx.x * 64;
    int b = row0 >> 10;
    int valid_len = length[b] + 1;
    if ((row0 & (SS - 1)) >= valid_len) return;

    __shared__ unsigned As[64][36];
    __shared__ unsigned Bs[32][136];
    __shared__ float redS[2][64];
    __shared__ float redQ[2][64];
    int t = threadIdx.x, w = t >> 5, lane = t & 31;
    int g = lane >> 2, tg = lane & 3, mq = w >> 1, nh = w & 1;

    float acc[8][4];
    #pragma unroll
    for (int i = 0; i < 8; i++) acc[i][0] = acc[i][1] = acc[i][2] = acc[i][3] = 0.f;

    for (int kc = 0; kc < DFF / 32; kc++) {
        __syncthreads();
        stage_As(As, g_h + (size_t)row0 * DFF + kc * 32, DFF, t);
        stage_Bs(Bs, W2 + (size_t)(kc * 32) * DD, DD, t);
        __syncthreads();
        compute_chunk(acc, As, Bs, mq, nh, g, tg);
    }

    int r0 = row0 + mq * 16 + g, r1 = r0 + 8;
    float rs0 = 0.f, rq0 = 0.f, rs1 = 0.f, rq1 = 0.f;
    #pragma unroll
    for (int nt = 0; nt < 8; nt++) {
        int col = nh * 64 + nt * 8 + 2 * tg;
        float2 bi = *(const float2*)&b2[col];
        float2 e0 = *(const float2*)&g_x[(size_t)r0 * DD + col];
        float2 e1 = *(const float2*)&g_x[(size_t)r1 * DD + col];
        acc[nt][0] += bi.x + e0.x;
        acc[nt][1] += bi.y + e0.y;
        acc[nt][2] += bi.x + e1.x;
        acc[nt][3] += bi.y + e1.y;
        rs0 += acc[nt][0] + acc[nt][1];
        rq0 += acc[nt][0] * acc[nt][0] + acc[nt][1] * acc[nt][1];
        rs1 += acc[nt][2] + acc[nt][3];
        rq1 += acc[nt][2] * acc[nt][2] + acc[nt][3] * acc[nt][3];
    }
    rs0 += __shfl_xor_sync(0xffffffff, rs0, 1);
    rs0 += __shfl_xor_sync(0xffffffff, rs0, 2);
    rq0 += __shfl_xor_sync(0xffffffff, rq0, 1);
    rq0 += __shfl_xor_sync(0xffffffff, rq0, 2);
    rs1 += __shfl_xor_sync(0xffffffff, rs1, 1);
    rs1 += __shfl_xor_sync(0xffffffff, rs1, 2);
    rq1 += __shfl_xor_sync(0xffffffff, rq1, 1);
    rq1 += __shfl_xor_sync(0xffffffff, rq1, 2);
    if (tg == 0) {
        redS[nh][mq * 16 + g] = rs0;
        redS[nh][mq * 16 + g + 8] = rs1;
        redQ[nh][mq * 16 + g] = rq0;
        redQ[nh][mq * 16 + g + 8] = rq1;
    }
    __syncthreads();
    float mu0 = (redS[0][mq * 16 + g] + redS[1][mq * 16 + g]) * (1.f / DD);
    float mu1 = (redS[0][mq * 16 + g + 8] + redS[1][mq * 16 + g + 8]) * (1.f / DD);
    float v0 = fmaxf((redQ[0][mq * 16 + g] + redQ[1][mq * 16 + g]) * (1.f / DD) - mu0 * mu0, 0.f);
    float v1 = fmaxf((redQ[0][mq * 16 + g + 8] + redQ[1][mq * 16 + g + 8]) * (1.f / DD) - mu1 * mu1, 0.f);
    float rst0 = rsqrtf(v0 + 1e-3f), rst1 = rsqrtf(v1 + 1e-3f);
    #pragma unroll
    for (int nt = 0; nt < 8; nt++) {
        int col = nh * 64 + nt * 8 + 2 * tg;
        float2 gm = *(const float2*)&g2[col];
        float2 bt = *(const float2*)&be2[col];
        float2 lo = {(acc[nt][0] - mu0) * rst0 * gm.x + bt.x,
                     (acc[nt][1] - mu0) * rst0 * gm.y + bt.y};
        float2 hi = {(acc[nt][2] - mu1) * rst1 * gm.x + bt.x,
                     (acc[nt][3] - mu1) * rst1 * gm.y + bt.y};
        *(float2*)&g_x[(size_t)r0 * DD + col] = lo;
        *(float2*)&g_x[(size_t)r1 * DD + col] = hi;
    }
}

// ---------------- masked mean-pool + MLP head + sigmoid ----------------
__global__ __launch_bounds__(256) void head_kernel(
    const int* __restrict__ length,
    const float* __restrict__ Wm1, const float* __restrict__ bm1,
    const float* __restrict__ Wm2, const float* __restrict__ bm2,
    float* __restrict__ out) {
    int b = blockIdx.x;
    int t = threadIdx.x;
    __shared__ float part[2][DD];
    __shared__ float agg[DD];
    __shared__ float hh[MLPH];
    __shared__ float red[8];
    int cnt = length[b] + 1;
    int d = t & 127, grp = t >> 7;
    float s0 = 0.f, s1 = 0.f, s2 = 0.f, s3 = 0.f;
    int ss = grp;
    for (; ss + 6 < cnt; ss += 8) {
        s0 += g_x[(b * SS + ss) * DD + d];
        s1 += g_x[(b * SS + ss + 2) * DD + d];
        s2 += g_x[(b * SS + ss + 4) * DD + d];
        s3 += g_x[(b * SS + ss + 6) * DD + d];
    }
    for (; ss < cnt; ss += 2) s0 += g_x[(b * SS + ss) * DD + d];
    part[grp][d] = s0 + s1 + s2 + s3;
    __syncthreads();
    if (t < DD) agg[t] = (part[0][t] + part[1][t]) / (float)cnt;
    __syncthreads();
    {
        float acc = bm1[t];
        #pragma unroll 8
        for (int k = 0; k < DD; k++) acc += agg[k] * Wm1[k * MLPH + t];
        hh[t] = fmaxf(acc, 0.f);
    }
    __syncthreads();
    float v = hh[t] * Wm2[t];
    #pragma unroll
    for (int o = 16; o > 0; o >>= 1) v += __shfl_xor_sync(0xffffffff, v, o);
    if ((t & 31) == 0) red[t >> 5] = v;
    __syncthreads();
    if (t == 0) {
        float s = 0.f;
        #pragma unroll
        for (int i = 0; i < 8; i++) s += red[i];
        s += bm2[0];
        out[b] = 1.f / (1.f + __expf(-s));
    }
}

// ---------------- launch ----------------
extern "C" void kernel_launch(void* const* d_in, const int* in_sizes, int n_in,
                              void* d_out, int out_size) {
    (void)in_sizes; (void)n_in; (void)out_size;
    const float* demo       = (const float*)d_in[0];
    const float* times      = (const float*)d_in[1];
    const float* values     = (const float*)d_in[2];
    const int*   length     = (const int*)d_in[3];
    const float* timescales = (const float*)d_in[4];
    const float* W_demo = (const float*)d_in[5];
    const float* b_demo = (const float*)d_in[6];
    const float* W_val  = (const float*)d_in[7];
    const float* b_val  = (const float*)d_in[8];
    const float* Wq = (const float*)d_in[9];
    const float* bq = (const float*)d_in[10];
    const float* Wk = (const float*)d_in[11];
    const float* bk = (const float*)d_in[12];
    const float* Wv = (const float*)d_in[13];
    const float* bv = (const float*)d_in[14];
    const float* Wo = (const float*)d_in[15];
    const float* bo = (const float*)d_in[16];
    const float* ln1g = (const float*)d_in[17];
    const float* ln1b = (const float*)d_in[18];
    const float* W1 = (const float*)d_in[19];
    const float* b1 = (const float*)d_in[20];
    const float* W2 = (const float*)d_in[21];
    const float* b2 = (const float*)d_in[22];
    const float* ln2g = (const float*)d_in[23];
    const float* ln2b = (const float*)d_in[24];
    const float* Wm1 = (const float*)d_in[25];
    const float* bm1 = (const float*)d_in[26];
    const float* Wm2 = (const float*)d_in[27];
    const float* bm2 = (const float*)d_in[28];
    float* out = (float*)d_out;

    embed_kernel<<<(BB * SS * DD + 255) / 256, 256>>>(
        demo, times, values, timescales, W_demo, b_demo, W_val, b_val, length);

    int ntiles = BB * SS / 64;
    for (int l = 0; l < NLAY; l++) {
        dim3 gq(ntiles, 3);
        qkv_mma_kernel<<<gq, 256>>>(length,
            Wq + l * DD * DD, bq + l * DD,
            Wk + l * DD * DD, bk + l * DD,
            Wv + l * DD * DD, bv + l * DD);
        dim3 ag(SS / 64, HH, BB);
        attn_mma_kernel<<<ag, 128>>>(length);
        oproj_ln_mma_kernel<<<ntiles, 256>>>(length,
            Wo + l * DD * DD, bo + l * DD, ln1g + l * DD, ln1b + l * DD);
        dim3 gf(ntiles, 4);
        ffn1_mma_kernel<<<gf, 256>>>(length, W1 + l * DD * DFF, b1 + l * DFF);
        ffn2_ln_mma_kernel<<<ntiles, 256>>>(length,
            W2 + l * DFF * DD, b2 + l * DD, ln2g + l * DD, ln2b + l * DD);
    }

    head_kernel<<<BB, 256>>>(length, Wm1, bm1, Wm2, bm2, out);
}